// round 4
// baseline (speedup 1.0000x reference)
#include <cuda_runtime.h>
#include <math.h>

// Problem constants (fixed shapes)
#define B_ROWS  65536
#define D_DIM   256
#define L_LVL   4
#define K_CODES 2048

// GEMM tiling: 128x128 tile, 128 threads, 8x16 microtile, BK=16
#define BM 128
#define BN 128
#define BK 16
#define NTHREADS 128
#define NT_TILES (K_CODES / BN)   // 16

// Scratch (allocation-free rule: __device__ globals)
__device__ float g_res[(size_t)B_ROWS * D_DIM];   // running residual, 64 MB
__device__ float g_e2[L_LVL * K_CODES];           // per-code squared norms

// Packed fp32 helpers (sm_100+): 2 IEEE fp32 FMAs per instruction
#define PACK_DUP(d, s) asm("mov.b64 %0, {%1, %1};" : "=l"(d) : "f"(s))
#define FMA2(acc, a, b) asm("fma.rn.f32x2 %0, %1, %2, %0;" : "+l"(acc) : "l"(a), "l"(b))
#define UNPACK2(lo, hi, v) asm("mov.b64 {%0, %1}, %2;" : "=f"(lo), "=f"(hi) : "l"(v))

// ---------------------------------------------------------------------------
// e2[l*K + k] = sum_d codebooks[l,k,d]^2  in fp64, rounded to fp32.
// ---------------------------------------------------------------------------
__global__ void e2_kernel(const float* __restrict__ codebooks)
{
    int warp = (blockIdx.x * blockDim.x + threadIdx.x) >> 5;
    int lane = threadIdx.x & 31;
    if (warp >= L_LVL * K_CODES) return;
    const float* p = codebooks + (size_t)warp * D_DIM;
    double s = 0.0;
    #pragma unroll
    for (int i = 0; i < D_DIM / 32; ++i) {
        double v = (double)p[lane + 32 * i];
        s += v * v;
    }
    #pragma unroll
    for (int o = 16; o; o >>= 1) s += __shfl_xor_sync(0xffffffffu, s, o);
    if (lane == 0) g_e2[warp] = (float)s;
}

// ---------------------------------------------------------------------------
// One RQ level. Score chain (matches reference rounding exactly):
//   S = fl( fl(x2 + e2[k]) - 2*dot ),  dot via fp32 fma chain (FFMA2 lanes
//   are IEEE fp32, same accumulation order per accumulator as the scalar ver).
// Ties break to lower code index (jnp.argmin first-occurrence).
// Then: res -= emb[idx];  quant = fl(quant + emb[idx]);  codes written.
// ---------------------------------------------------------------------------
__global__ __launch_bounds__(NTHREADS, 2)
void rq_level_kernel(const float* __restrict__ residual,   // original input [B,D]
                     const float* __restrict__ codebooks,  // [L,K,D]
                     float* __restrict__ quant,            // [B,D] running qsum (d_out)
                     float* __restrict__ codes_out,        // [B,L] written as float
                     int level)
{
    __shared__ float As[BK][BM + 4];   // res chunk, K-major
    __shared__ float Bs[BK][BN + 4];   // emb chunk, K-major
    __shared__ float redV[BM][8];
    __shared__ int   redI[BM][8];
    __shared__ float sh_x2[BM];

    const float* res_in  = (level == 0) ? residual : g_res;
    float*       res_out = g_res;
    const float* emb = codebooks + (size_t)level * K_CODES * D_DIM;
    const float* e2  = g_e2 + level * K_CODES;

    const int tid  = threadIdx.x;
    const int nIdx = tid & 7;           // 0..7  (16-col group)
    const int mIdx = tid >> 3;          // 0..15 (8-row group)
    const int bm   = blockIdx.x * BM;

    const int ldd = tid & 15;           // d within BK chunk for tile loads
    const int ldr = tid >> 4;           // base row for tile loads (0..7)

    // ---- per-row x2 = sum(res^2) in fp64 -> fp32 (1 thread per row) ----
    {
        const float* p = res_in + (size_t)(bm + tid) * D_DIM;
        double s0 = 0.0, s1 = 0.0, s2 = 0.0, s3 = 0.0;
        #pragma unroll 8
        for (int i = 0; i < D_DIM; i += 4) {
            double v0 = (double)p[i + 0], v1 = (double)p[i + 1];
            double v2 = (double)p[i + 2], v3 = (double)p[i + 3];
            s0 += v0 * v0; s1 += v1 * v1; s2 += v2 * v2; s3 += v3 * v3;
        }
        sh_x2[tid] = (float)((s0 + s1) + (s2 + s3));
    }
    __syncthreads();

    float x2v[8];
    #pragma unroll
    for (int i = 0; i < 8; ++i) x2v[i] = sh_x2[mIdx * 8 + i];

    float minV[8];
    int   minI[8];
    #pragma unroll
    for (int i = 0; i < 8; ++i) { minV[i] = INFINITY; minI[i] = 0; }

    for (int nt = 0; nt < NT_TILES; ++nt) {
        unsigned long long acc2[8][8];   // [row i][col-pair j2], lanes = cols (2*j2, 2*j2+1)
        #pragma unroll
        for (int i = 0; i < 8; ++i)
            #pragma unroll
            for (int j = 0; j < 8; ++j) acc2[i][j] = 0ull;

        for (int dc = 0; dc < D_DIM; dc += BK) {
            __syncthreads();   // previous compute done before overwrite
            #pragma unroll
            for (int i = 0; i < BM / 8; ++i) {
                int r = ldr + 8 * i;
                As[ldd][r] = res_in[(size_t)(bm + r) * D_DIM + dc + ldd];
                Bs[ldd][r] = emb[(size_t)(nt * BN + r) * D_DIM + dc + ldd];
            }
            __syncthreads();

            #pragma unroll 4
            for (int kk = 0; kk < BK; ++kk) {
                const float4 a0 = *(const float4*)(&As[kk][mIdx * 8]);
                const float4 a1 = *(const float4*)(&As[kk][mIdx * 8 + 4]);
                unsigned long long aD[8];
                PACK_DUP(aD[0], a0.x); PACK_DUP(aD[1], a0.y);
                PACK_DUP(aD[2], a0.z); PACK_DUP(aD[3], a0.w);
                PACK_DUP(aD[4], a1.x); PACK_DUP(aD[5], a1.y);
                PACK_DUP(aD[6], a1.z); PACK_DUP(aD[7], a1.w);

                const ulonglong2 bq0 = *(const ulonglong2*)(&Bs[kk][nIdx * 16 + 0]);
                const ulonglong2 bq1 = *(const ulonglong2*)(&Bs[kk][nIdx * 16 + 4]);
                const ulonglong2 bq2 = *(const ulonglong2*)(&Bs[kk][nIdx * 16 + 8]);
                const ulonglong2 bq3 = *(const ulonglong2*)(&Bs[kk][nIdx * 16 + 12]);
                const unsigned long long bP[8] =
                    { bq0.x, bq0.y, bq1.x, bq1.y, bq2.x, bq2.y, bq3.x, bq3.y };

                #pragma unroll
                for (int i = 0; i < 8; ++i)
                    #pragma unroll
                    for (int j = 0; j < 8; ++j)
                        FMA2(acc2[i][j], aD[i], bP[j]);
            }
        }

        // epilogue: S = fl(fl(x2 + e2[k]) - 2*dot); running argmin, ascending k
        #pragma unroll
        for (int q = 0; q < 8; ++q) {
            int c0 = nIdx * 16 + 2 * q;
            int g0 = nt * BN + c0;
            float ek0 = __ldg(&e2[g0]);
            float ek1 = __ldg(&e2[g0 + 1]);
            #pragma unroll
            for (int i = 0; i < 8; ++i) {
                float dlo, dhi;
                UNPACK2(dlo, dhi, acc2[i][q]);
                float A0 = __fadd_rn(x2v[i], ek0);
                float s0 = __fmaf_rn(-2.0f, dlo, A0);
                if (s0 < minV[i]) { minV[i] = s0; minI[i] = g0; }
                float A1 = __fadd_rn(x2v[i], ek1);
                float s1 = __fmaf_rn(-2.0f, dhi, A1);
                if (s1 < minV[i]) { minV[i] = s1; minI[i] = g0 + 1; }
            }
        }
    }

    // cross-thread argmin reduction (8 candidates per row), lexicographic
    __syncthreads();
    #pragma unroll
    for (int i = 0; i < 8; ++i) {
        redV[mIdx * 8 + i][nIdx] = minV[i];
        redI[mIdx * 8 + i][nIdx] = minI[i];
    }
    __syncthreads();

    {
        float bv = redV[tid][0];
        int   bi = redI[tid][0];
        #pragma unroll
        for (int j = 1; j < 8; ++j) {
            float v = redV[tid][j];
            int  ix = redI[tid][j];
            if (v < bv || (v == bv && ix < bi)) { bv = v; bi = ix; }
        }
        redI[tid][0] = bi;
        codes_out[(size_t)(bm + tid) * L_LVL + level] = (float)bi;
    }
    __syncthreads();

    // residual update + qsum accumulation, coalesced (float4 granularity)
    #pragma unroll
    for (int it = 0; it < (BM * D_DIM / 4) / NTHREADS; ++it) {
        int f  = tid + NTHREADS * it;      // float4 index within block tile
        int r  = f >> 6;                   // 64 float4 per row
        int d4 = f & 63;
        int q  = redI[r][0];
        size_t off = (size_t)(bm + r) * D_DIM + d4 * 4;
        float4 a = *(const float4*)(res_in + off);
        float4 e = *(const float4*)(emb + (size_t)q * D_DIM + d4 * 4);
        *(float4*)(res_out + off) =
            make_float4(__fadd_rn(a.x, -e.x), __fadd_rn(a.y, -e.y),
                        __fadd_rn(a.z, -e.z), __fadd_rn(a.w, -e.w));
        if (level == 0) {
            *(float4*)(quant + off) = e;   // qsum = fl(0 + q) = q
        } else {
            float4 p = *(const float4*)(quant + off);
            *(float4*)(quant + off) =
                make_float4(__fadd_rn(p.x, e.x), __fadd_rn(p.y, e.y),
                            __fadd_rn(p.z, e.z), __fadd_rn(p.w, e.w));
        }
    }
}

// ---------------------------------------------------------------------------
extern "C" void kernel_launch(void* const* d_in, const int* in_sizes, int n_in,
                              void* d_out, int out_size)
{
    const float* residual  = (const float*)d_in[0];   // [B, D] float32
    const float* codebooks = (const float*)d_in[1];   // [L, K, D] float32
    float* out   = (float*)d_out;
    float* quant = out;                               // [B, D]
    float* codes = out + (size_t)B_ROWS * D_DIM;      // [B, L] as float

    e2_kernel<<<(L_LVL * K_CODES * 32 + 255) / 256, 256>>>(codebooks);

    for (int l = 0; l < L_LVL; ++l)
        rq_level_kernel<<<B_ROWS / BM, NTHREADS>>>(residual, codebooks, quant, codes, l);
}

// round 5
// speedup vs baseline: 1.5736x; 1.5736x over previous
#include <cuda_runtime.h>
#include <math.h>

// Problem constants (fixed shapes)
#define B_ROWS  65536
#define D_DIM   256
#define L_LVL   4
#define K_CODES 2048

// GEMM tiling: 128x128 tile, 128 threads, 8x16 microtile (FFMA2 col pairs), BK=16
#define BM 128
#define BN 128
#define BK 16
#define NTHREADS 128
#define NT_TILES (K_CODES / BN)   // 16

// Scratch (allocation-free rule: __device__ globals)
__device__ float g_res[(size_t)B_ROWS * D_DIM];   // running residual, 64 MB
__device__ float g_e2[L_LVL * K_CODES];           // per-code squared norms

// Packed fp32 (sm_100+): 2 IEEE fp32 FMAs per instruction, double-rate vs FFMA
#define PACK_DUP(d, s) asm("mov.b64 %0, {%1, %1};" : "=l"(d) : "f"(s))
#define FMA2(acc, a, b) asm("fma.rn.f32x2 %0, %1, %2, %0;" : "+l"(acc) : "l"(a), "l"(b))
#define UNPACK2(lo, hi, v) asm("mov.b64 {%0, %1}, %2;" : "=f"(lo), "=f"(hi) : "l"(v))

// ---------------------------------------------------------------------------
// e2[l*K + k] = sum_d codebooks[l,k,d]^2  in fp64, rounded to fp32.
// ---------------------------------------------------------------------------
__global__ void e2_kernel(const float* __restrict__ codebooks)
{
    int warp = (blockIdx.x * blockDim.x + threadIdx.x) >> 5;
    int lane = threadIdx.x & 31;
    if (warp >= L_LVL * K_CODES) return;
    const float* p = codebooks + (size_t)warp * D_DIM;
    double s = 0.0;
    #pragma unroll
    for (int i = 0; i < D_DIM / 32; ++i) {
        double v = (double)p[lane + 32 * i];
        s += v * v;
    }
    #pragma unroll
    for (int o = 16; o; o >>= 1) s += __shfl_xor_sync(0xffffffffu, s, o);
    if (lane == 0) g_e2[warp] = (float)s;
}

// ---------------------------------------------------------------------------
// One RQ level. Score chain matches the reference rounding exactly:
//   S = fl( fl(x2 + e2[k]) - 2*dot ); dot = fp32 fma chain, ascending k.
// FFMA2 lanes are IEEE fp32 single-rounded -> bit-identical to scalar chain.
// Ties break to lower code index (jnp.argmin first-occurrence).
// ---------------------------------------------------------------------------
__global__ __launch_bounds__(NTHREADS, 2)
void rq_level_kernel(const float* __restrict__ residual,   // original input [B,D]
                     const float* __restrict__ codebooks,  // [L,K,D]
                     float* __restrict__ quant,            // [B,D] running qsum (d_out)
                     float* __restrict__ codes_out,        // [B,L] as float
                     int level)
{
    __shared__ float As[BK][BM + 4];   // res chunk, K-major
    __shared__ float Bs[BK][BN + 4];   // emb chunk, K-major
    __shared__ float redV[BM][8];
    __shared__ int   redI[BM][8];
    __shared__ float sh_x2[BM];

    const float* res_in  = (level == 0) ? residual : g_res;
    float*       res_out = g_res;
    const float* emb = codebooks + (size_t)level * K_CODES * D_DIM;
    const float* e2  = g_e2 + level * K_CODES;

    const int tid  = threadIdx.x;
    const int nIdx = tid & 7;           // 0..7  : cols seg*32 + nIdx*4 + {0..3}, seg=0..3
    const int mIdx = tid >> 3;          // 0..15 : rows mIdx*4 + {0..3} + {0,64}
    const int bm   = blockIdx.x * BM;

    const int ldd = tid & 15;           // d within BK chunk for tile loads
    const int ldr = tid >> 4;           // base row for tile loads (0..7)

    // ---- per-row x2 = sum(res^2) in fp64 -> fp32 (1 thread per row) ----
    {
        const float* p = res_in + (size_t)(bm + tid) * D_DIM;
        double s0 = 0.0, s1 = 0.0, s2 = 0.0, s3 = 0.0;
        #pragma unroll 8
        for (int i = 0; i < D_DIM; i += 4) {
            double v0 = (double)p[i + 0], v1 = (double)p[i + 1];
            double v2 = (double)p[i + 2], v3 = (double)p[i + 3];
            s0 += v0 * v0; s1 += v1 * v1; s2 += v2 * v2; s3 += v3 * v3;
        }
        sh_x2[tid] = (float)((s0 + s1) + (s2 + s3));
    }
    __syncthreads();

    float x2v[8];
    #pragma unroll
    for (int i = 0; i < 8; ++i) {
        int r = (i < 4) ? (mIdx * 4 + i) : (64 + mIdx * 4 + (i - 4));
        x2v[i] = sh_x2[r];
    }

    float minV[8];
    int   minI[8];
    #pragma unroll
    for (int i = 0; i < 8; ++i) { minV[i] = INFINITY; minI[i] = 0; }

    for (int nt = 0; nt < NT_TILES; ++nt) {
        // acc2[i][seg*2+u] accumulates cols (seg*32 + nIdx*4 + 2u, +1) for row i
        unsigned long long acc2[8][8];
        #pragma unroll
        for (int i = 0; i < 8; ++i)
            #pragma unroll
            for (int j = 0; j < 8; ++j) acc2[i][j] = 0ull;

        for (int dc = 0; dc < D_DIM; dc += BK) {
            __syncthreads();   // previous compute done before overwrite
            #pragma unroll
            for (int i = 0; i < BM / 8; ++i) {
                int r = ldr + 8 * i;
                As[ldd][r] = res_in[(size_t)(bm + r) * D_DIM + dc + ldd];
                Bs[ldd][r] = emb[(size_t)(nt * BN + r) * D_DIM + dc + ldd];
            }
            __syncthreads();

            #pragma unroll 4
            for (int kk = 0; kk < BK; ++kk) {
                // a rows: 16B-stride chunks, 8-way broadcast -> conflict-free
                const float4 a0 = *(const float4*)(&As[kk][mIdx * 4]);
                const float4 a1 = *(const float4*)(&As[kk][64 + mIdx * 4]);
                unsigned long long aD[8];
                PACK_DUP(aD[0], a0.x); PACK_DUP(aD[1], a0.y);
                PACK_DUP(aD[2], a0.z); PACK_DUP(aD[3], a0.w);
                PACK_DUP(aD[4], a1.x); PACK_DUP(aD[5], a1.y);
                PACK_DUP(aD[6], a1.z); PACK_DUP(aD[7], a1.w);

                // b cols: 16B stride over 8 lanes = contiguous 128B per phase
                const ulonglong2 b0 = *(const ulonglong2*)(&Bs[kk][ 0 + nIdx * 4]);
                const ulonglong2 b1 = *(const ulonglong2*)(&Bs[kk][32 + nIdx * 4]);
                const ulonglong2 b2 = *(const ulonglong2*)(&Bs[kk][64 + nIdx * 4]);
                const ulonglong2 b3 = *(const ulonglong2*)(&Bs[kk][96 + nIdx * 4]);
                const unsigned long long bP[8] =
                    { b0.x, b0.y, b1.x, b1.y, b2.x, b2.y, b3.x, b3.y };

                #pragma unroll
                for (int i = 0; i < 8; ++i)
                    #pragma unroll
                    for (int j = 0; j < 8; ++j)
                        FMA2(acc2[i][j], aD[i], bP[j]);
            }
        }

        // epilogue: S = fl(fl(x2 + e2[k]) - 2*dot); running argmin, ascending k
        #pragma unroll
        for (int j = 0; j < 8; ++j) {
            int seg = j >> 1, u = j & 1;
            int c0 = seg * 32 + nIdx * 4 + 2 * u;
            int g0 = nt * BN + c0;
            float ek0 = __ldg(&e2[g0]);
            float ek1 = __ldg(&e2[g0 + 1]);
            #pragma unroll
            for (int i = 0; i < 8; ++i) {
                float dlo, dhi;
                UNPACK2(dlo, dhi, acc2[i][j]);
                float A0 = __fadd_rn(x2v[i], ek0);
                float s0 = __fmaf_rn(-2.0f, dlo, A0);
                if (s0 < minV[i]) { minV[i] = s0; minI[i] = g0; }
                float A1 = __fadd_rn(x2v[i], ek1);
                float s1 = __fmaf_rn(-2.0f, dhi, A1);
                if (s1 < minV[i]) { minV[i] = s1; minI[i] = g0 + 1; }
            }
        }
    }

    // cross-thread argmin reduction (8 candidates per row), lexicographic
    __syncthreads();
    #pragma unroll
    for (int i = 0; i < 8; ++i) {
        int r = (i < 4) ? (mIdx * 4 + i) : (64 + mIdx * 4 + (i - 4));
        redV[r][nIdx] = minV[i];
        redI[r][nIdx] = minI[i];
    }
    __syncthreads();

    {
        float bv = redV[tid][0];
        int   bi = redI[tid][0];
        #pragma unroll
        for (int j = 1; j < 8; ++j) {
            float v = redV[tid][j];
            int  ix = redI[tid][j];
            if (v < bv || (v == bv && ix < bi)) { bv = v; bi = ix; }
        }
        redI[tid][0] = bi;
        codes_out[(size_t)(bm + tid) * L_LVL + level] = (float)bi;
    }
    __syncthreads();

    // residual update + qsum accumulation, coalesced (float4 granularity)
    #pragma unroll
    for (int it = 0; it < (BM * D_DIM / 4) / NTHREADS; ++it) {
        int f  = tid + NTHREADS * it;      // float4 index within block tile
        int r  = f >> 6;                   // 64 float4 per row
        int d4 = f & 63;
        int q  = redI[r][0];
        size_t off = (size_t)(bm + r) * D_DIM + d4 * 4;
        float4 a = *(const float4*)(res_in + off);
        float4 e = *(const float4*)(emb + (size_t)q * D_DIM + d4 * 4);
        *(float4*)(res_out + off) =
            make_float4(__fadd_rn(a.x, -e.x), __fadd_rn(a.y, -e.y),
                        __fadd_rn(a.z, -e.z), __fadd_rn(a.w, -e.w));
        if (level == 0) {
            *(float4*)(quant + off) = e;   // qsum = fl(0 + q) = q
        } else {
            float4 p = *(const float4*)(quant + off);
            *(float4*)(quant + off) =
                make_float4(__fadd_rn(p.x, e.x), __fadd_rn(p.y, e.y),
                            __fadd_rn(p.z, e.z), __fadd_rn(p.w, e.w));
        }
    }
}

// ---------------------------------------------------------------------------
extern "C" void kernel_launch(void* const* d_in, const int* in_sizes, int n_in,
                              void* d_out, int out_size)
{
    const float* residual  = (const float*)d_in[0];   // [B, D] float32
    const float* codebooks = (const float*)d_in[1];   // [L, K, D] float32
    float* out   = (float*)d_out;
    float* quant = out;                               // [B, D]
    float* codes = out + (size_t)B_ROWS * D_DIM;      // [B, L] as float

    e2_kernel<<<(L_LVL * K_CODES * 32 + 255) / 256, 256>>>(codebooks);

    for (int l = 0; l < L_LVL; ++l)
        rq_level_kernel<<<B_ROWS / BM, NTHREADS>>>(residual, codebooks, quant, codes, l);
}

// round 6
// speedup vs baseline: 1.7837x; 1.1335x over previous
#include <cuda_runtime.h>
#include <math.h>

// Problem constants (fixed shapes)
#define B_ROWS  65536
#define D_DIM   256
#define L_LVL   4
#define K_CODES 2048

// GEMM tiling: 128x128 tile, 256 threads, 8x8 microtile (FFMA2 col pairs), BK=16
#define BM 128
#define BN 128
#define BK 16
#define NTHREADS 256
#define NT_TILES (K_CODES / BN)   // 16
#define NCHUNK   (D_DIM / BK)     // 16

// Scratch (allocation-free rule: __device__ globals)
__device__ float g_res[(size_t)B_ROWS * D_DIM];   // running residual, 64 MB
__device__ float g_e2[L_LVL * K_CODES];           // per-code squared norms

// Packed fp32 (sm_100+): 2 IEEE fp32 FMAs per instruction (halves issue count)
#define PACK_DUP(d, s) asm("mov.b64 %0, {%1, %1};" : "=l"(d) : "f"(s))
#define FMA2(acc, a, b) asm("fma.rn.f32x2 %0, %1, %2, %0;" : "+l"(acc) : "l"(a), "l"(b))
#define UNPACK2(lo, hi, v) asm("mov.b64 {%0, %1}, %2;" : "=f"(lo), "=f"(hi) : "l"(v))

// ---------------------------------------------------------------------------
// e2[l*K + k] = sum_d codebooks[l,k,d]^2  in fp64, rounded to fp32.
// ---------------------------------------------------------------------------
__global__ void e2_kernel(const float* __restrict__ codebooks)
{
    int warp = (blockIdx.x * blockDim.x + threadIdx.x) >> 5;
    int lane = threadIdx.x & 31;
    if (warp >= L_LVL * K_CODES) return;
    const float* p = codebooks + (size_t)warp * D_DIM;
    double s = 0.0;
    #pragma unroll
    for (int i = 0; i < D_DIM / 32; ++i) {
        double v = (double)p[lane + 32 * i];
        s += v * v;
    }
    #pragma unroll
    for (int o = 16; o; o >>= 1) s += __shfl_xor_sync(0xffffffffu, s, o);
    if (lane == 0) g_e2[warp] = (float)s;
}

// ---------------------------------------------------------------------------
// One RQ level. Score chain matches the reference rounding exactly:
//   S = fl( fl(x2 + e2[k]) - 2*dot ); dot = fp32 fma chain, ascending k.
// Ties break to lower code index (jnp.argmin first-occurrence).
// Double-buffered smem pipeline: 1 barrier per BK-chunk, LDG prefetch of the
// next chunk overlaps compute of the current one.
// ---------------------------------------------------------------------------
__global__ __launch_bounds__(NTHREADS, 2)
void rq_level_kernel(const float* __restrict__ residual,   // original input [B,D]
                     const float* __restrict__ codebooks,  // [L,K,D]
                     float* __restrict__ quant,            // [B,D] running qsum (d_out)
                     float* __restrict__ codes_out,        // [B,L] as float
                     int level)
{
    __shared__ float As[2][BK][BM + 4];   // res chunk, K-major, double-buffered
    __shared__ float Bs[2][BK][BN + 4];   // emb chunk, K-major, double-buffered
    __shared__ float redV[BM][16];
    __shared__ int   redI[BM][16];
    __shared__ float sh_x2[BM];

    const float* res_in  = (level == 0) ? residual : g_res;
    float*       res_out = g_res;
    const float* emb = codebooks + (size_t)level * K_CODES * D_DIM;
    const float* e2  = g_e2 + level * K_CODES;

    const int tid  = threadIdx.x;
    const int nIdx = tid & 15;          // 0..15 : cols {nIdx*4..+3} U {64+nIdx*4..+3}
    const int mIdx = tid >> 4;          // 0..15 : rows {mIdx*4..+3} U {64+mIdx*4..+3}
    const int bm   = blockIdx.x * BM;

    const int ldd = tid & 15;           // d within BK chunk for tile loads
    const int ldr = tid >> 4;           // base row for tile loads (0..15)

    // ---- per-row x2 = sum(res^2) in fp64 -> fp32 (2 threads per row) ----
    {
        int r = tid >> 1;
        int h = tid & 1;
        const float* p = res_in + (size_t)(bm + r) * D_DIM + h * 128;
        double s0 = 0.0, s1 = 0.0;
        #pragma unroll 16
        for (int i = 0; i < 128; i += 2) {
            double v0 = (double)p[i], v1 = (double)p[i + 1];
            s0 += v0 * v0; s1 += v1 * v1;
        }
        double s = s0 + s1;
        s += __shfl_xor_sync(0xffffffffu, s, 1);
        if (h == 0) sh_x2[r] = (float)s;
    }
    __syncthreads();

    float minV[8];
    int   minI[8];
    #pragma unroll
    for (int i = 0; i < 8; ++i) { minV[i] = INFINITY; minI[i] = 0; }

    const float* aG = res_in + (size_t)bm * D_DIM;

    for (int nt = 0; nt < NT_TILES; ++nt) {
        const float* bG = emb + (size_t)(nt * BN) * D_DIM;

        // acc2[i][j]: j=0,1 -> col pairs (nIdx*4+0,1),(nIdx*4+2,3)
        //             j=2,3 -> (64+nIdx*4+0,1),(64+nIdx*4+2,3)
        unsigned long long acc2[8][4];
        #pragma unroll
        for (int i = 0; i < 8; ++i)
            #pragma unroll
            for (int j = 0; j < 4; ++j) acc2[i][j] = 0ull;

        float ra[8], rb[8];
        // prologue: fetch + store chunk 0
        #pragma unroll
        for (int i = 0; i < 8; ++i) {
            int r = ldr + 16 * i;
            ra[i] = aG[(size_t)r * D_DIM + ldd];
            rb[i] = bG[(size_t)r * D_DIM + ldd];
        }
        #pragma unroll
        for (int i = 0; i < 8; ++i) {
            int r = ldr + 16 * i;
            As[0][ldd][r] = ra[i];
            Bs[0][ldd][r] = rb[i];
        }
        __syncthreads();

        #pragma unroll 2
        for (int c = 0; c < NCHUNK; ++c) {
            const int cur = c & 1;
            // prefetch next chunk into registers (overlaps with compute)
            if (c < NCHUNK - 1) {
                int dc = (c + 1) * BK;
                #pragma unroll
                for (int i = 0; i < 8; ++i) {
                    int r = ldr + 16 * i;
                    ra[i] = aG[(size_t)r * D_DIM + dc + ldd];
                    rb[i] = bG[(size_t)r * D_DIM + dc + ldd];
                }
            }
            // compute current chunk
            #pragma unroll 8
            for (int kk = 0; kk < BK; ++kk) {
                const float4 a0 = *(const float4*)(&As[cur][kk][mIdx * 4]);
                const float4 a1 = *(const float4*)(&As[cur][kk][64 + mIdx * 4]);
                const ulonglong2 b0 = *(const ulonglong2*)(&Bs[cur][kk][nIdx * 4]);
                const ulonglong2 b1 = *(const ulonglong2*)(&Bs[cur][kk][64 + nIdx * 4]);
                unsigned long long aD[8];
                PACK_DUP(aD[0], a0.x); PACK_DUP(aD[1], a0.y);
                PACK_DUP(aD[2], a0.z); PACK_DUP(aD[3], a0.w);
                PACK_DUP(aD[4], a1.x); PACK_DUP(aD[5], a1.y);
                PACK_DUP(aD[6], a1.z); PACK_DUP(aD[7], a1.w);
                const unsigned long long bP[4] = { b0.x, b0.y, b1.x, b1.y };
                #pragma unroll
                for (int i = 0; i < 8; ++i)
                    #pragma unroll
                    for (int j = 0; j < 4; ++j)
                        FMA2(acc2[i][j], aD[i], bP[j]);
            }
            // store prefetched chunk into the other buffer (that buffer was
            // last READ in chunk c-1's compute; the barrier below chunk c-1
            // already ordered all those reads before these writes)
            if (c < NCHUNK - 1) {
                const int nxt = (c + 1) & 1;
                #pragma unroll
                for (int i = 0; i < 8; ++i) {
                    int r = ldr + 16 * i;
                    As[nxt][ldd][r] = ra[i];
                    Bs[nxt][ldd][r] = rb[i];
                }
            }
            __syncthreads();
        }

        // epilogue: S = fl(fl(x2 + e2[k]) - 2*dot); running argmin, ascending k
        #pragma unroll
        for (int j = 0; j < 4; ++j) {
            int c0 = (j < 2) ? (nIdx * 4 + 2 * j) : (64 + nIdx * 4 + 2 * (j - 2));
            int g0 = nt * BN + c0;
            float ek0 = __ldg(&e2[g0]);
            float ek1 = __ldg(&e2[g0 + 1]);
            #pragma unroll
            for (int i = 0; i < 8; ++i) {
                int r = (i < 4) ? (mIdx * 4 + i) : (64 + mIdx * 4 + (i - 4));
                float x2r = sh_x2[r];
                float dlo, dhi;
                UNPACK2(dlo, dhi, acc2[i][j]);
                float A0 = __fadd_rn(x2r, ek0);
                float s0 = __fmaf_rn(-2.0f, dlo, A0);
                if (s0 < minV[i]) { minV[i] = s0; minI[i] = g0; }
                float A1 = __fadd_rn(x2r, ek1);
                float s1 = __fmaf_rn(-2.0f, dhi, A1);
                if (s1 < minV[i]) { minV[i] = s1; minI[i] = g0 + 1; }
            }
        }
    }

    // cross-thread argmin reduction (16 candidates per row), lexicographic
    __syncthreads();
    #pragma unroll
    for (int i = 0; i < 8; ++i) {
        int r = (i < 4) ? (mIdx * 4 + i) : (64 + mIdx * 4 + (i - 4));
        redV[r][nIdx] = minV[i];
        redI[r][nIdx] = minI[i];
    }
    __syncthreads();

    if (tid < BM) {
        float bv = redV[tid][0];
        int   bi = redI[tid][0];
        #pragma unroll
        for (int j = 1; j < 16; ++j) {
            float v = redV[tid][j];
            int  ix = redI[tid][j];
            if (v < bv || (v == bv && ix < bi)) { bv = v; bi = ix; }
        }
        redI[tid][0] = bi;
        codes_out[(size_t)(bm + tid) * L_LVL + level] = (float)bi;
    }
    __syncthreads();

    // residual update + qsum accumulation, coalesced (float4 granularity)
    #pragma unroll
    for (int it = 0; it < (BM * D_DIM / 4) / NTHREADS; ++it) {
        int f  = tid + NTHREADS * it;      // float4 index within block tile
        int r  = f >> 6;                   // 64 float4 per row
        int d4 = f & 63;
        int q  = redI[r][0];
        size_t off = (size_t)(bm + r) * D_DIM + d4 * 4;
        float4 a = *(const float4*)(res_in + off);
        float4 e = *(const float4*)(emb + (size_t)q * D_DIM + d4 * 4);
        *(float4*)(res_out + off) =
            make_float4(__fadd_rn(a.x, -e.x), __fadd_rn(a.y, -e.y),
                        __fadd_rn(a.z, -e.z), __fadd_rn(a.w, -e.w));
        if (level == 0) {
            *(float4*)(quant + off) = e;   // qsum = fl(0 + q) = q
        } else {
            float4 p = *(const float4*)(quant + off);
            *(float4*)(quant + off) =
                make_float4(__fadd_rn(p.x, e.x), __fadd_rn(p.y, e.y),
                            __fadd_rn(p.z, e.z), __fadd_rn(p.w, e.w));
        }
    }
}

// ---------------------------------------------------------------------------
extern "C" void kernel_launch(void* const* d_in, const int* in_sizes, int n_in,
                              void* d_out, int out_size)
{
    const float* residual  = (const float*)d_in[0];   // [B, D] float32
    const float* codebooks = (const float*)d_in[1];   // [L, K, D] float32
    float* out   = (float*)d_out;
    float* quant = out;                               // [B, D]
    float* codes = out + (size_t)B_ROWS * D_DIM;      // [B, L] as float

    e2_kernel<<<(L_LVL * K_CODES * 32 + 255) / 256, 256>>>(codebooks);

    for (int l = 0; l < L_LVL; ++l)
        rq_level_kernel<<<B_ROWS / BM, NTHREADS>>>(residual, codebooks, quant, codes, l);
}